// round 16
// baseline (speedup 1.0000x reference)
#include <cuda_runtime.h>
#include <cuda_fp16.h>
#include <cstdint>

#define HEADS  8
#define DIMH   64
#define BATCH  16
#define CDIM   512
#define HW     4096
#define HIDDEN 512
#define NSPLIT 16
#define BH_TOT (BATCH * HEADS)

// ---------------- scratch (no allocations allowed) ----------------
__device__ __half g_x16[(size_t)BATCH * CDIM * HW];           // 67 MB, x fp16 natural [b][c][n]
__device__ __half g_part[(size_t)NSPLIT * BH_TOT * DIMH * DIMH]; // 16.8 MB fp16 ctx partials
__device__ float  g_sums[(size_t)NSPLIT * BH_TOT * DIMH];     // 0.5 MB
__device__ __half g_mcat[(size_t)BATCH * HIDDEN * HIDDEN];
__device__ __half g_mcomb[(size_t)BATCH * HIDDEN * CDIM];
__device__ __half g_wkv[(size_t)2 * HIDDEN * CDIM];           // head-blocked [h][k64;v64][512]
__device__ __half g_wq16[(size_t)HIDDEN * CDIM];              // Wq natural fp16

// ================= PTX helpers =================
__device__ __forceinline__ uint32_t smem_u32(const void* p) {
    uint32_t a;
    asm("{ .reg .u64 t; cvta.to.shared.u64 t, %1; cvt.u32.u64 %0, t; }"
        : "=r"(a) : "l"(p));
    return a;
}
__device__ __forceinline__ void cp_async16(uint32_t dst, const void* src) {
    asm volatile("cp.async.cg.shared.global [%0], [%1], 16;"
                 :: "r"(dst), "l"(src));
}
#define CP_COMMIT() asm volatile("cp.async.commit_group;")
#define CP_WAIT(n)  asm volatile("cp.async.wait_group %0;" :: "n"(n))

__device__ __forceinline__ void ldmx4(uint32_t* r, uint32_t addr) {
    asm volatile("ldmatrix.sync.aligned.m8n8.x4.shared.b16 {%0,%1,%2,%3}, [%4];"
                 : "=r"(r[0]), "=r"(r[1]), "=r"(r[2]), "=r"(r[3]) : "r"(addr));
}
__device__ __forceinline__ void ldmx4t(uint32_t* r, uint32_t addr) {
    asm volatile("ldmatrix.sync.aligned.m8n8.x4.trans.shared.b16 {%0,%1,%2,%3}, [%4];"
                 : "=r"(r[0]), "=r"(r[1]), "=r"(r[2]), "=r"(r[3]) : "r"(addr));
}
__device__ __forceinline__ void mma16816(float* d, const uint32_t* a,
                                         uint32_t b0, uint32_t b1) {
    asm volatile(
        "mma.sync.aligned.m16n8k16.row.col.f32.f16.f16.f32 "
        "{%0,%1,%2,%3}, {%4,%5,%6,%7}, {%8,%9}, {%0,%1,%2,%3};"
        : "+f"(d[0]), "+f"(d[1]), "+f"(d[2]), "+f"(d[3])
        : "r"(a[0]), "r"(a[1]), "r"(a[2]), "r"(a[3]), "r"(b0), "r"(b1));
}

// packed f32x2
__device__ __forceinline__ unsigned long long f32x2_dup(float a) {
    unsigned long long r;
    asm("mov.b64 %0, {%1, %1};" : "=l"(r) : "f"(a));
    return r;
}
__device__ __forceinline__ unsigned long long f32x2_fma(unsigned long long a,
                                                        unsigned long long b,
                                                        unsigned long long c) {
    unsigned long long d;
    asm("fma.rn.f32x2 %0, %1, %2, %3;" : "=l"(d) : "l"(a), "l"(b), "l"(c));
    return d;
}
__device__ __forceinline__ float2 f32x2_unpack(unsigned long long v) {
    float2 f;
    asm("mov.b64 {%0, %1}, %2;" : "=f"(f.x), "=f"(f.y) : "l"(v));
    return f;
}

// ================= GEMM config =================
#define AROWB 80
#define BROWB 272
#define A_TILE (128 * AROWB)                 // 10240
#define B_TILE (32 * BROWB)                  // 8704
#define STAGE_BYTES (A_TILE + B_TILE)        // 18944
#define NSTAGE 4
#define GEMM_SMEM (NSTAGE * STAGE_BYTES)     // 75776
// epilogue fp16 tiles: KT [64c][128n], VT [64d][128n], rows 272B
#define CROWB 272
#define KT_OFF 0
#define VT_OFF (64 * CROWB)                  // 17408 bytes

// ====== GEMM1 + fused ctx (HMMA epilogue), 2 n-windows per CTA ======
__global__ __launch_bounds__(128, 2) void gemm1ctx_kernel(
    const __half* __restrict__ Ah, const __half* __restrict__ B_,
    __half* __restrict__ part, float* __restrict__ sums)
{
    constexpr int K = CDIM, N = HW;
    extern __shared__ char smem[];
    const uint32_t sb = smem_u32(smem);

    const int t = threadIdx.x;
    const int lane = t & 31, wid = t >> 5;
    const int m_off = (wid & 1) * 64, n_off = (wid >> 1) * 64;
    const int m0 = blockIdx.y * 128;          // head block
    const int n0base = blockIdx.x * 256;      // split window (2x128)
    const long z = blockIdx.z;
    const __half* Bh = B_ + z * (long)CDIM * HW;

    const uint32_t aBase = sb + (uint32_t)((m_off + (lane & 15)) * AROWB + (lane >> 4) * 16);
    const uint32_t bBase = sb + A_TILE +
        (uint32_t)(((lane & 7) + ((lane >> 3) & 1) * 8) * BROWB +
                   ((lane >> 4) & 1) * 16 + n_off * 2);

    // cross-window accumulators
    float accc[8][4];
    #pragma unroll
    for (int j = 0; j < 8; j++)
        #pragma unroll
        for (int r = 0; r < 4; r++) accc[j][r] = 0.f;
    float ksum_reg = 0.f;

    const int lr = lane >> 2;
    const int lc = (lane & 3) * 2;
    const int isV = wid & 1;
    const int c_off = wid * 16;
    const uint32_t aB2 = sb + KT_OFF +
        (uint32_t)((c_off + (lane & 15)) * CROWB + (lane >> 4) * 16);
    const uint32_t bB2 = sb + VT_OFF +
        (uint32_t)(((lane & 7) + ((lane >> 4) << 3)) * CROWB + ((lane >> 3) & 1) * 16);

    #pragma unroll 1
    for (int w = 0; w < 2; w++) {
        const int n0 = n0base + w * 128;

        float acc[4][8][4];
        #pragma unroll
        for (int i = 0; i < 4; i++)
            #pragma unroll
            for (int j = 0; j < 8; j++)
                #pragma unroll
                for (int r = 0; r < 4; r++) acc[i][j][r] = 0.f;

        const int nst = K / 32;

        auto load_stage = [&](int s) {
            const int k0 = s * 32;
            const uint32_t bufb = sb + (uint32_t)((s % NSTAGE) * STAGE_BYTES);
            #pragma unroll
            for (int p = 0; p < 4; p++) {                  // A: 128 rows x 64B
                int row = (t >> 2) + p * 32;
                cp_async16(bufb + (uint32_t)(row * AROWB + (t & 3) * 16),
                           Ah + (long)(m0 + row) * K + k0 + (t & 3) * 8);
            }
            #pragma unroll
            for (int p = 0; p < 4; p++) {                  // B: 32 rows x 256B
                int idx = t + p * 128;
                int krow = idx >> 4, nch = idx & 15;
                cp_async16(bufb + A_TILE + (uint32_t)(krow * BROWB + nch * 16),
                           Bh + (long)(k0 + krow) * N + n0 + nch * 8);
            }
            CP_COMMIT();
        };

        #pragma unroll
        for (int s = 0; s < NSTAGE - 1; s++) load_stage(s);

        for (int s = 0; s < nst; s++) {
            if (s + NSTAGE - 1 < nst) { load_stage(s + NSTAGE - 1); CP_WAIT(NSTAGE - 2); }
            else                      { CP_WAIT(0); }
            __syncthreads();

            const uint32_t bufo = (uint32_t)((s % NSTAGE) * STAGE_BYTES);
            #pragma unroll
            for (int ks = 0; ks < 2; ks++) {
                uint32_t bh[16];
                #pragma unroll
                for (int nj = 0; nj < 4; nj++)
                    ldmx4t(&bh[nj * 4], bBase + bufo + (uint32_t)(ks * 16 * BROWB + nj * 32));
                #pragma unroll
                for (int mi = 0; mi < 4; mi++) {
                    uint32_t ah[4];
                    ldmx4(ah, aBase + bufo + (uint32_t)(mi * 16 * AROWB + ks * 32));
                    #pragma unroll
                    for (int j = 0; j < 8; j++) {
                        int bi = (j >> 1) * 4 + (j & 1) * 2;
                        mma16816(acc[mi][j], ah, bh[bi], bh[bi + 1]);
                    }
                }
            }
            __syncthreads();
        }

        // ---- stash fragments: KT = exp(k), VT = v (fp16, [row][128n]) ----
        {
            char* base = smem + (isV ? VT_OFF : KT_OFF);
            #pragma unroll
            for (int mi = 0; mi < 4; mi++)
                #pragma unroll
                for (int hf = 0; hf < 2; hf++) {
                    int r = mi * 16 + hf * 8 + lr;
                    #pragma unroll
                    for (int j = 0; j < 8; j++) {
                        int n = n_off + j * 8 + lc;
                        float a = acc[mi][j][hf * 2 + 0];
                        float b = acc[mi][j][hf * 2 + 1];
                        __half2 hv = isV ? __floats2half2_rn(a, b)
                                         : __floats2half2_rn(__expf(a), __expf(b));
                        *(__half2*)(base + r * CROWB + n * 2) = hv;
                    }
                }
        }
        __syncthreads();

        // row sums of exp(k): 64 threads, one KT row each (accumulate reg)
        if (t < 64) {
            const uint4* rp = (const uint4*)(smem + KT_OFF + t * CROWB);
            float s = 0.f;
            #pragma unroll
            for (int i = 0; i < 16; i++) {
                uint4 v = rp[i];
                float2 f;
                f = __half22float2(*(__half2*)&v.x); s += f.x + f.y;
                f = __half22float2(*(__half2*)&v.y); s += f.x + f.y;
                f = __half22float2(*(__half2*)&v.z); s += f.x + f.y;
                f = __half22float2(*(__half2*)&v.w); s += f.x + f.y;
            }
            ksum_reg += s;
        }

        // ctx accumulate: KT @ VT^T (m=64 c, n=64 d, k=128 n)
        #pragma unroll
        for (int ks = 0; ks < 8; ks++) {
            uint32_t ah[4];
            ldmx4(ah, aB2 + (uint32_t)(ks * 32));
            uint32_t bh2[16];
            #pragma unroll
            for (int nj = 0; nj < 4; nj++)
                ldmx4(&bh2[nj * 4], bB2 + (uint32_t)(nj * 16 * CROWB + ks * 32));
            #pragma unroll
            for (int j = 0; j < 8; j++) {
                int bi = (j >> 1) * 4 + (j & 1) * 2;
                mma16816(accc[j], ah, bh2[bi], bh2[bi + 1]);
            }
        }
        __syncthreads();   // KT/VT dead before next window's cp.async reuse
    }

    const int bh_idx = (int)z * HEADS + blockIdx.y;
    const int split = blockIdx.x;

    if (t < 64)
        sums[((long)split * BH_TOT + bh_idx) * 64 + t] = ksum_reg;

    __half* dst = part + ((long)split * BH_TOT + bh_idx) * 4096;
    const int cr = c_off + (lane >> 2);
    const int dc = (lane & 3) * 2;
    #pragma unroll
    for (int j = 0; j < 8; j++) {
        int d = dc + j * 8;
        *(__half2*)&dst[cr * 64 + d] =
            __floats2half2_rn(accc[j][0], accc[j][1]);
        *(__half2*)&dst[(cr + 8) * 64 + d] =
            __floats2half2_rn(accc[j][2], accc[j][3]);
    }
}

// ======== generic fp16 HMMA GEMM: C[z] = A[z] @ B[z] (+bias), B is [k][n] ====
template<typename OutT>
__global__ __launch_bounds__(128, 2) void gemm_g_kernel(
    const __half* __restrict__ A_, const __half* __restrict__ B_,
    OutT* __restrict__ C, const float* __restrict__ bias,
    int M, int N, int K, long sA, long sB, long sC)
{
    extern __shared__ char smem[];
    const uint32_t sb = smem_u32(smem);

    const int t = threadIdx.x;
    const int lane = t & 31, wid = t >> 5;
    const int m_off = (wid & 1) * 64, n_off = (wid >> 1) * 64;
    const int m0 = blockIdx.y * 128, n0 = blockIdx.x * 128;
    const long z = blockIdx.z;
    const __half* Ah = A_ + z * sA;
    const __half* Bh = B_ + z * sB;

    const uint32_t aBase = sb + (uint32_t)((m_off + (lane & 15)) * AROWB + (lane >> 4) * 16);
    const uint32_t bBase = sb + A_TILE +
        (uint32_t)(((lane & 7) + ((lane >> 3) & 1) * 8) * BROWB +
                   ((lane >> 4) & 1) * 16 + n_off * 2);

    float acc[4][8][4];
    #pragma unroll
    for (int i = 0; i < 4; i++)
        #pragma unroll
        for (int j = 0; j < 8; j++)
            #pragma unroll
            for (int r = 0; r < 4; r++) acc[i][j][r] = 0.f;

    const int nst = K / 32;

    auto load_stage = [&](int s) {
        const int k0 = s * 32;
        const uint32_t bufb = sb + (uint32_t)((s % NSTAGE) * STAGE_BYTES);
        #pragma unroll
        for (int p = 0; p < 4; p++) {
            int row = (t >> 2) + p * 32;
            cp_async16(bufb + (uint32_t)(row * AROWB + (t & 3) * 16),
                       Ah + (long)(m0 + row) * K + k0 + (t & 3) * 8);
        }
        #pragma unroll
        for (int p = 0; p < 4; p++) {
            int idx = t + p * 128;
            int krow = idx >> 4, nch = idx & 15;
            cp_async16(bufb + A_TILE + (uint32_t)(krow * BROWB + nch * 16),
                       Bh + (long)(k0 + krow) * N + n0 + nch * 8);
        }
        CP_COMMIT();
    };

    #pragma unroll
    for (int s = 0; s < NSTAGE - 1; s++) load_stage(s);

    for (int s = 0; s < nst; s++) {
        if (s + NSTAGE - 1 < nst) { load_stage(s + NSTAGE - 1); CP_WAIT(NSTAGE - 2); }
        else                      { CP_WAIT(0); }
        __syncthreads();

        const uint32_t bufo = (uint32_t)((s % NSTAGE) * STAGE_BYTES);
        #pragma unroll
        for (int ks = 0; ks < 2; ks++) {
            uint32_t bh[16];
            #pragma unroll
            for (int nj = 0; nj < 4; nj++)
                ldmx4t(&bh[nj * 4], bBase + bufo + (uint32_t)(ks * 16 * BROWB + nj * 32));
            #pragma unroll
            for (int mi = 0; mi < 4; mi++) {
                uint32_t ah[4];
                ldmx4(ah, aBase + bufo + (uint32_t)(mi * 16 * AROWB + ks * 32));
                #pragma unroll
                for (int j = 0; j < 8; j++) {
                    int bi = (j >> 1) * 4 + (j & 1) * 2;
                    mma16816(acc[mi][j], ah, bh[bi], bh[bi + 1]);
                }
            }
        }
        __syncthreads();
    }

    OutT* Cz = C + z * sC;
    const int mrow = m0 + m_off + (lane >> 2);
    const int ncol = n0 + n_off + (lane & 3) * 2;
    #pragma unroll
    for (int mi = 0; mi < 4; mi++) {
        int r0 = mrow + mi * 16;
        float bv0 = bias ? bias[r0] : 0.f;
        float bv1 = bias ? bias[r0 + 8] : 0.f;
        #pragma unroll
        for (int j = 0; j < 8; j++) {
            int cc = ncol + j * 8;
            if constexpr (sizeof(OutT) == 4) {
                *(float2*)(Cz + (long)r0 * N + cc) =
                    make_float2(acc[mi][j][0] + bv0, acc[mi][j][1] + bv0);
                *(float2*)(Cz + (long)(r0 + 8) * N + cc) =
                    make_float2(acc[mi][j][2] + bv1, acc[mi][j][3] + bv1);
            } else {
                *(__half2*)(Cz + (long)r0 * N + cc) =
                    __floats2half2_rn(acc[mi][j][0] + bv0, acc[mi][j][1] + bv0);
                *(__half2*)(Cz + (long)(r0 + 8) * N + cc) =
                    __floats2half2_rn(acc[mi][j][2] + bv1, acc[mi][j][3] + bv1);
            }
        }
    }
}

// ========== merged conversion kernel (x16 | wq16 | wkv) ==========
#define XBLK 16384
#define WQBLK 128
#define WKVBLK 512
__global__ __launch_bounds__(256) void conv_all_kernel(
    const float* __restrict__ x, const float* __restrict__ w_qkv,
    __half* __restrict__ x16, __half* __restrict__ wq16,
    __half* __restrict__ wkv)
{
    int bid = blockIdx.x;
    if (bid < XBLK) {
        long i = ((long)bid * 256 + threadIdx.x) * 8;
        float4 a = *(const float4*)(x + i);
        float4 b = *(const float4*)(x + i + 4);
        __half2 h0 = __floats2half2_rn(a.x, a.y), h1 = __floats2half2_rn(a.z, a.w);
        __half2 h2 = __floats2half2_rn(b.x, b.y), h3 = __floats2half2_rn(b.z, b.w);
        uint4 o;
        o.x = *(uint32_t*)&h0; o.y = *(uint32_t*)&h1;
        o.z = *(uint32_t*)&h2; o.w = *(uint32_t*)&h3;
        *(uint4*)(x16 + i) = o;
    } else if (bid < XBLK + WQBLK) {
        long i = ((long)(bid - XBLK) * 256 + threadIdx.x) * 8;
        float4 a = *(const float4*)(w_qkv + i);
        float4 b = *(const float4*)(w_qkv + i + 4);
        __half2 h0 = __floats2half2_rn(a.x, a.y), h1 = __floats2half2_rn(a.z, a.w);
        __half2 h2 = __floats2half2_rn(b.x, b.y), h3 = __floats2half2_rn(b.z, b.w);
        uint4 o;
        o.x = *(uint32_t*)&h0; o.y = *(uint32_t*)&h1;
        o.z = *(uint32_t*)&h2; o.w = *(uint32_t*)&h3;
        *(uint4*)(wq16 + i) = o;
    } else {
        int i = (bid - XBLK - WQBLK) * 256 + threadIdx.x;  // float4 groups
        int r_new = i >> 7;
        int colg = i & 127;
        int h = r_new >> 7, wr = r_new & 127;
        int src_row = (wr < 64) ? (HIDDEN + h * 64 + wr)
                                : (2 * HIDDEN + h * 64 + (wr - 64));
        float4 a = *(const float4*)(w_qkv + (long)src_row * CDIM + colg * 4);
        __half2 h0 = __floats2half2_rn(a.x, a.y), h1 = __floats2half2_rn(a.z, a.w);
        *(__half2*)(wkv + (long)r_new * CDIM + colg * 4)     = h0;
        *(__half2*)(wkv + (long)r_new * CDIM + colg * 4 + 2) = h1;
    }
}

// == Mcat[b][o][h*64+c] = sum_d w_out[o][h*64+d] * ctx_norm[b][h][c][d] ==
__global__ __launch_bounds__(256) void mcat_kernel(const float* __restrict__ wo,
                                                   const __half* __restrict__ part,
                                                   const float* __restrict__ sums,
                                                   __half* __restrict__ mcat)
{
    __shared__ float ctxs[64][66];
    __shared__ float wos[64][66];
    __shared__ float invs[64];
    int bh = blockIdx.x;
    int b = bh >> 3, h = bh & 7;
    int t = threadIdx.x;
    int og = (t >> 4) * 4, cg = (t & 15) * 4;

    if (t < 64) {
        float s = 0.f;
        #pragma unroll 8
        for (int sp = 0; sp < NSPLIT; sp++)
            s += sums[((long)sp * BH_TOT + bh) * 64 + t];
        invs[t] = 1.0f / s;
    }
    __syncthreads();
    for (int i0 = t * 2; i0 < 4096; i0 += 512) {
        float sx = 0.f, sy = 0.f;
        #pragma unroll 8
        for (int sp = 0; sp < NSPLIT; sp++) {
            __half2 hp = *(const __half2*)&part[((long)sp * BH_TOT + bh) * 4096 + i0];
            float2 f = __half22float2(hp);
            sx += f.x; sy += f.y;
        }
        int c = i0 >> 6, d = i0 & 63;
        ctxs[c][d]     = sx * invs[c];
        ctxs[c][d + 1] = sy * invs[c];
    }

    for (int o0 = 0; o0 < HIDDEN; o0 += 64) {
        __syncthreads();
        for (int i = t; i < 4096; i += 256)
            wos[i >> 6][i & 63] = wo[(long)(o0 + (i >> 6)) * HIDDEN + h * 64 + (i & 63)];
        __syncthreads();

        unsigned long long acc2[4][4];
        #pragma unroll
        for (int i = 0; i < 4; i++)
            #pragma unroll
            for (int j = 0; j < 4; j++) acc2[i][j] = 0ull;

        #pragma unroll 8
        for (int d2 = 0; d2 < 64; d2 += 2) {
            unsigned long long av[4], bv[4];
            #pragma unroll
            for (int i = 0; i < 4; i++)
                av[i] = *(const unsigned long long*)&wos[og + i][d2];
            #pragma unroll
            for (int j = 0; j < 4; j++)
                bv[j] = *(const unsigned long long*)&ctxs[cg + j][d2];
            #pragma unroll
            for (int i = 0; i < 4; i++)
                #pragma unroll
                for (int j = 0; j < 4; j++)
                    acc2[i][j] = f32x2_fma(av[i], bv[j], acc2[i][j]);
        }
        #pragma unroll
        for (int i = 0; i < 4; i++) {
            float r[4];
            #pragma unroll
            for (int j = 0; j < 4; j++) {
                float2 p = f32x2_unpack(acc2[i][j]);
                r[j] = p.x + p.y;
            }
            __half* dp = mcat + ((long)b * HIDDEN + o0 + og + i) * HIDDEN + h * 64 + cg;
            *(__half2*)(dp)     = __floats2half2_rn(r[0], r[1]);
            *(__half2*)(dp + 2) = __floats2half2_rn(r[2], r[3]);
        }
    }
}

// ================= launch =================
extern "C" void kernel_launch(void* const* d_in, const int* in_sizes, int n_in,
                              void* d_out, int out_size)
{
    const float* x     = (const float*)d_in[0];   // (16,512,64,64)
    const float* w_qkv = (const float*)d_in[1];   // (1536,512): [q;k;v]
    const float* w_out = (const float*)d_in[2];   // (512,512)
    const float* b_out = (const float*)d_in[3];   // (512,)
    float* y = (float*)d_out;

    float* sums;
    __half *x16, *part, *mcat, *mcomb, *wkv, *wq16;
    cudaGetSymbolAddress((void**)&x16,   g_x16);
    cudaGetSymbolAddress((void**)&part,  g_part);
    cudaGetSymbolAddress((void**)&sums,  g_sums);
    cudaGetSymbolAddress((void**)&mcat,  g_mcat);
    cudaGetSymbolAddress((void**)&mcomb, g_mcomb);
    cudaGetSymbolAddress((void**)&wkv,   g_wkv);
    cudaGetSymbolAddress((void**)&wq16,  g_wq16);

    cudaFuncSetAttribute(gemm1ctx_kernel,
                         cudaFuncAttributeMaxDynamicSharedMemorySize, GEMM_SMEM);
    cudaFuncSetAttribute(gemm_g_kernel<__half>,
                         cudaFuncAttributeMaxDynamicSharedMemorySize, GEMM_SMEM);
    cudaFuncSetAttribute(gemm_g_kernel<float>,
                         cudaFuncAttributeMaxDynamicSharedMemorySize, GEMM_SMEM);

    // 0. all conversions in one launch
    conv_all_kernel<<<XBLK + WQBLK + WKVBLK, 256>>>(x, w_qkv, x16, wq16, wkv);

    // 1. fused [k;v] GEMM + exp + ctx partials (2 windows/CTA) + row sums
    gemm1ctx_kernel<<<dim3(NSPLIT, HEADS, BATCH), 128, GEMM_SMEM>>>(
        wkv, x16, part, sums);

    // 2. Mcat = (W_out per-head) @ normalize(ctx)^T  (split-reduce fused)
    mcat_kernel<<<BH_TOT, 256>>>(w_out, part, sums, mcat);

    // 3. Mcomb[b] = Mcat[b] @ Wq   (B = Wq natural [k][n])
    gemm_g_kernel<__half><<<dim3(CDIM / 128, HIDDEN / 128, BATCH), 128, GEMM_SMEM>>>(
        mcat, wq16, mcomb, nullptr,
        HIDDEN, CDIM, HIDDEN,
        (long)HIDDEN * HIDDEN, 0L, (long)HIDDEN * CDIM);

    // 4. y = Mcomb @ x + b_out   (B = x16 natural [c][n])
    gemm_g_kernel<float><<<dim3(HW / 128, HIDDEN / 128, BATCH), 128, GEMM_SMEM>>>(
        mcomb, x16, y, b_out,
        HIDDEN, HW, CDIM,
        (long)HIDDEN * CDIM, (long)CDIM * HW, (long)HIDDEN * HW);
}

// round 17
// speedup vs baseline: 1.0346x; 1.0346x over previous
#include <cuda_runtime.h>
#include <cuda_fp16.h>
#include <cstdint>

#define HEADS  8
#define DIMH   64
#define BATCH  16
#define CDIM   512
#define HW     4096
#define HIDDEN 512
#define NSPLIT 32
#define BH_TOT (BATCH * HEADS)

// ---------------- scratch (no allocations allowed) ----------------
__device__ __half g_x16[(size_t)BATCH * CDIM * HW];           // 67 MB, x fp16 natural [b][c][n]
__device__ __half g_part[(size_t)NSPLIT * BH_TOT * DIMH * DIMH]; // 33.5 MB fp16 ctx partials
__device__ float  g_sums[(size_t)NSPLIT * BH_TOT * DIMH];     // 1 MB
__device__ __half g_mcat[(size_t)BATCH * HIDDEN * HIDDEN];
__device__ __half g_mcomb[(size_t)BATCH * HIDDEN * CDIM];
__device__ __half g_wkv[(size_t)2 * HIDDEN * CDIM];           // head-blocked [h][k64;v64][512]
__device__ __half g_wq16[(size_t)HIDDEN * CDIM];              // Wq natural fp16

// ================= PTX helpers =================
__device__ __forceinline__ uint32_t smem_u32(const void* p) {
    uint32_t a;
    asm("{ .reg .u64 t; cvta.to.shared.u64 t, %1; cvt.u32.u64 %0, t; }"
        : "=r"(a) : "l"(p));
    return a;
}
__device__ __forceinline__ void cp_async16(uint32_t dst, const void* src) {
    asm volatile("cp.async.cg.shared.global [%0], [%1], 16;"
                 :: "r"(dst), "l"(src));
}
#define CP_COMMIT() asm volatile("cp.async.commit_group;")
#define CP_WAIT(n)  asm volatile("cp.async.wait_group %0;" :: "n"(n))

__device__ __forceinline__ void ldmx4(uint32_t* r, uint32_t addr) {
    asm volatile("ldmatrix.sync.aligned.m8n8.x4.shared.b16 {%0,%1,%2,%3}, [%4];"
                 : "=r"(r[0]), "=r"(r[1]), "=r"(r[2]), "=r"(r[3]) : "r"(addr));
}
__device__ __forceinline__ void ldmx4t(uint32_t* r, uint32_t addr) {
    asm volatile("ldmatrix.sync.aligned.m8n8.x4.trans.shared.b16 {%0,%1,%2,%3}, [%4];"
                 : "=r"(r[0]), "=r"(r[1]), "=r"(r[2]), "=r"(r[3]) : "r"(addr));
}
__device__ __forceinline__ void mma16816(float* d, const uint32_t* a,
                                         uint32_t b0, uint32_t b1) {
    asm volatile(
        "mma.sync.aligned.m16n8k16.row.col.f32.f16.f16.f32 "
        "{%0,%1,%2,%3}, {%4,%5,%6,%7}, {%8,%9}, {%0,%1,%2,%3};"
        : "+f"(d[0]), "+f"(d[1]), "+f"(d[2]), "+f"(d[3])
        : "r"(a[0]), "r"(a[1]), "r"(a[2]), "r"(a[3]), "r"(b0), "r"(b1));
}

// packed f32x2
__device__ __forceinline__ unsigned long long f32x2_dup(float a) {
    unsigned long long r;
    asm("mov.b64 %0, {%1, %1};" : "=l"(r) : "f"(a));
    return r;
}
__device__ __forceinline__ unsigned long long f32x2_fma(unsigned long long a,
                                                        unsigned long long b,
                                                        unsigned long long c) {
    unsigned long long d;
    asm("fma.rn.f32x2 %0, %1, %2, %3;" : "=l"(d) : "l"(a), "l"(b), "l"(c));
    return d;
}
__device__ __forceinline__ float2 f32x2_unpack(unsigned long long v) {
    float2 f;
    asm("mov.b64 {%0, %1}, %2;" : "=f"(f.x), "=f"(f.y) : "l"(v));
    return f;
}

// ================= GEMM config =================
#define AROWB 80
#define BROWB 272
#define A_TILE (128 * AROWB)                 // 10240
#define B_TILE (32 * BROWB)                  // 8704
#define STAGE_BYTES (A_TILE + B_TILE)        // 18944
#define NSTAGE 4
#define GEMM_SMEM (NSTAGE * STAGE_BYTES)     // 75776
// epilogue fp16 tiles: KT [64c][128n], VT [64d][128n], rows 272B
#define CROWB 272
#define KT_OFF 0
#define VT_OFF (64 * CROWB)                  // 17408 bytes

// ====== GEMM1 + fused ctx (HMMA epilogue) ======
__global__ __launch_bounds__(128, 2) void gemm1ctx_kernel(
    const __half* __restrict__ Ah, const __half* __restrict__ B_,
    __half* __restrict__ part, float* __restrict__ sums)
{
    constexpr int K = CDIM, N = HW;
    extern __shared__ char smem[];
    const uint32_t sb = smem_u32(smem);

    const int t = threadIdx.x;
    const int lane = t & 31, wid = t >> 5;
    const int m_off = (wid & 1) * 64, n_off = (wid >> 1) * 64;
    const int m0 = blockIdx.y * 128;          // head block
    const int n0 = blockIdx.x * 128;          // split window
    const long z = blockIdx.z;
    const __half* Bh = B_ + z * (long)CDIM * HW;

    const uint32_t aBase = sb + (uint32_t)((m_off + (lane & 15)) * AROWB + (lane >> 4) * 16);
    const uint32_t bBase = sb + A_TILE +
        (uint32_t)(((lane & 7) + ((lane >> 3) & 1) * 8) * BROWB +
                   ((lane >> 4) & 1) * 16 + n_off * 2);

    float acc[4][8][4];
    #pragma unroll
    for (int i = 0; i < 4; i++)
        #pragma unroll
        for (int j = 0; j < 8; j++)
            #pragma unroll
            for (int r = 0; r < 4; r++) acc[i][j][r] = 0.f;

    const int nst = K / 32;

    auto load_stage = [&](int s) {
        const int k0 = s * 32;
        const uint32_t bufb = sb + (uint32_t)((s % NSTAGE) * STAGE_BYTES);
        #pragma unroll
        for (int p = 0; p < 4; p++) {                  // A: 128 rows x 64B
            int row = (t >> 2) + p * 32;
            cp_async16(bufb + (uint32_t)(row * AROWB + (t & 3) * 16),
                       Ah + (long)(m0 + row) * K + k0 + (t & 3) * 8);
        }
        #pragma unroll
        for (int p = 0; p < 4; p++) {                  // B: 32 rows x 256B
            int idx = t + p * 128;
            int krow = idx >> 4, nch = idx & 15;
            cp_async16(bufb + A_TILE + (uint32_t)(krow * BROWB + nch * 16),
                       Bh + (long)(k0 + krow) * N + n0 + nch * 8);
        }
        CP_COMMIT();
    };

    #pragma unroll
    for (int s = 0; s < NSTAGE - 1; s++) load_stage(s);

    for (int s = 0; s < nst; s++) {
        if (s + NSTAGE - 1 < nst) { load_stage(s + NSTAGE - 1); CP_WAIT(NSTAGE - 2); }
        else                      { CP_WAIT(0); }
        __syncthreads();

        const uint32_t bufo = (uint32_t)((s % NSTAGE) * STAGE_BYTES);
        #pragma unroll
        for (int ks = 0; ks < 2; ks++) {
            uint32_t bh[16];
            #pragma unroll
            for (int nj = 0; nj < 4; nj++)
                ldmx4t(&bh[nj * 4], bBase + bufo + (uint32_t)(ks * 16 * BROWB + nj * 32));
            #pragma unroll
            for (int mi = 0; mi < 4; mi++) {
                uint32_t ah[4];
                ldmx4(ah, aBase + bufo + (uint32_t)(mi * 16 * AROWB + ks * 32));
                #pragma unroll
                for (int j = 0; j < 8; j++) {
                    int bi = (j >> 1) * 4 + (j & 1) * 2;
                    mma16816(acc[mi][j], ah, bh[bi], bh[bi + 1]);
                }
            }
        }
        __syncthreads();
    }

    // ---- fused ctx epilogue: fp16 tiles + HMMA ----
    const int lr = lane >> 2;
    const int lc = (lane & 3) * 2;
    const int isV = wid & 1;
    {
        char* base = smem + (isV ? VT_OFF : KT_OFF);
        #pragma unroll
        for (int mi = 0; mi < 4; mi++)
            #pragma unroll
            for (int hf = 0; hf < 2; hf++) {
                int r = mi * 16 + hf * 8 + lr;            // c (k half) or d (v half)
                #pragma unroll
                for (int j = 0; j < 8; j++) {
                    int n = n_off + j * 8 + lc;
                    float a = acc[mi][j][hf * 2 + 0];
                    float b = acc[mi][j][hf * 2 + 1];
                    __half2 hv = isV ? __floats2half2_rn(a, b)
                                     : __floats2half2_rn(__expf(a), __expf(b));
                    *(__half2*)(base + r * CROWB + n * 2) = hv;
                }
            }
    }
    __syncthreads();

    const int bh_idx = (int)z * HEADS + blockIdx.y;
    const int split = blockIdx.x;

    // row sums of exp(k): 64 threads, one KT row each
    if (t < 64) {
        const uint4* rp = (const uint4*)(smem + KT_OFF + t * CROWB);
        float s = 0.f;
        #pragma unroll
        for (int i = 0; i < 16; i++) {
            uint4 v = rp[i];
            float2 f;
            f = __half22float2(*(__half2*)&v.x); s += f.x + f.y;
            f = __half22float2(*(__half2*)&v.y); s += f.x + f.y;
            f = __half22float2(*(__half2*)&v.z); s += f.x + f.y;
            f = __half22float2(*(__half2*)&v.w); s += f.x + f.y;
        }
        sums[((long)split * BH_TOT + bh_idx) * 64 + t] = s;
    }

    // ctx[c][d] = KT @ VT^T : m=64(c), n=64(d), k=128(n). Warp w: c-slice 16.
    const int c_off = wid * 16;
    const uint32_t aB2 = sb + KT_OFF +
        (uint32_t)((c_off + (lane & 15)) * CROWB + (lane >> 4) * 16);
    const uint32_t bB2 = sb + VT_OFF +
        (uint32_t)(((lane & 7) + ((lane >> 4) << 3)) * CROWB + ((lane >> 3) & 1) * 16);

    float accc[8][4];
    #pragma unroll
    for (int j = 0; j < 8; j++)
        #pragma unroll
        for (int r = 0; r < 4; r++) accc[j][r] = 0.f;

    #pragma unroll
    for (int ks = 0; ks < 8; ks++) {
        uint32_t ah[4];
        ldmx4(ah, aB2 + (uint32_t)(ks * 32));
        uint32_t bh2[16];
        #pragma unroll
        for (int nj = 0; nj < 4; nj++)
            ldmx4(&bh2[nj * 4], bB2 + (uint32_t)(nj * 16 * CROWB + ks * 32));
        #pragma unroll
        for (int j = 0; j < 8; j++) {
            int bi = (j >> 1) * 4 + (j & 1) * 2;
            mma16816(accc[j], ah, bh2[bi], bh2[bi + 1]);
        }
    }

    __half* dst = part + ((long)split * BH_TOT + bh_idx) * 4096;
    const int cr = c_off + (lane >> 2);
    const int dc = (lane & 3) * 2;
    #pragma unroll
    for (int j = 0; j < 8; j++) {
        int d = dc + j * 8;
        *(__half2*)&dst[cr * 64 + d] =
            __floats2half2_rn(accc[j][0], accc[j][1]);
        *(__half2*)&dst[(cr + 8) * 64 + d] =
            __floats2half2_rn(accc[j][2], accc[j][3]);
    }
}

// ======== generic fp16 HMMA GEMM: C[z] = A[z] @ B[z] (+bias), B is [k][n] ====
template<typename OutT>
__global__ __launch_bounds__(128, 2) void gemm_g_kernel(
    const __half* __restrict__ A_, const __half* __restrict__ B_,
    OutT* __restrict__ C, const float* __restrict__ bias,
    int M, int N, int K, long sA, long sB, long sC)
{
    extern __shared__ char smem[];
    const uint32_t sb = smem_u32(smem);

    const int t = threadIdx.x;
    const int lane = t & 31, wid = t >> 5;
    const int m_off = (wid & 1) * 64, n_off = (wid >> 1) * 64;
    const int m0 = blockIdx.y * 128, n0 = blockIdx.x * 128;
    const long z = blockIdx.z;
    const __half* Ah = A_ + z * sA;
    const __half* Bh = B_ + z * sB;

    const uint32_t aBase = sb + (uint32_t)((m_off + (lane & 15)) * AROWB + (lane >> 4) * 16);
    const uint32_t bBase = sb + A_TILE +
        (uint32_t)(((lane & 7) + ((lane >> 3) & 1) * 8) * BROWB +
                   ((lane >> 4) & 1) * 16 + n_off * 2);

    float acc[4][8][4];
    #pragma unroll
    for (int i = 0; i < 4; i++)
        #pragma unroll
        for (int j = 0; j < 8; j++)
            #pragma unroll
            for (int r = 0; r < 4; r++) acc[i][j][r] = 0.f;

    const int nst = K / 32;

    auto load_stage = [&](int s) {
        const int k0 = s * 32;
        const uint32_t bufb = sb + (uint32_t)((s % NSTAGE) * STAGE_BYTES);
        #pragma unroll
        for (int p = 0; p < 4; p++) {
            int row = (t >> 2) + p * 32;
            cp_async16(bufb + (uint32_t)(row * AROWB + (t & 3) * 16),
                       Ah + (long)(m0 + row) * K + k0 + (t & 3) * 8);
        }
        #pragma unroll
        for (int p = 0; p < 4; p++) {
            int idx = t + p * 128;
            int krow = idx >> 4, nch = idx & 15;
            cp_async16(bufb + A_TILE + (uint32_t)(krow * BROWB + nch * 16),
                       Bh + (long)(k0 + krow) * N + n0 + nch * 8);
        }
        CP_COMMIT();
    };

    #pragma unroll
    for (int s = 0; s < NSTAGE - 1; s++) load_stage(s);

    for (int s = 0; s < nst; s++) {
        if (s + NSTAGE - 1 < nst) { load_stage(s + NSTAGE - 1); CP_WAIT(NSTAGE - 2); }
        else                      { CP_WAIT(0); }
        __syncthreads();

        const uint32_t bufo = (uint32_t)((s % NSTAGE) * STAGE_BYTES);
        #pragma unroll
        for (int ks = 0; ks < 2; ks++) {
            uint32_t bh[16];
            #pragma unroll
            for (int nj = 0; nj < 4; nj++)
                ldmx4t(&bh[nj * 4], bBase + bufo + (uint32_t)(ks * 16 * BROWB + nj * 32));
            #pragma unroll
            for (int mi = 0; mi < 4; mi++) {
                uint32_t ah[4];
                ldmx4(ah, aBase + bufo + (uint32_t)(mi * 16 * AROWB + ks * 32));
                #pragma unroll
                for (int j = 0; j < 8; j++) {
                    int bi = (j >> 1) * 4 + (j & 1) * 2;
                    mma16816(acc[mi][j], ah, bh[bi], bh[bi + 1]);
                }
            }
        }
        __syncthreads();
    }

    OutT* Cz = C + z * sC;
    const int mrow = m0 + m_off + (lane >> 2);
    const int ncol = n0 + n_off + (lane & 3) * 2;
    #pragma unroll
    for (int mi = 0; mi < 4; mi++) {
        int r0 = mrow + mi * 16;
        float bv0 = bias ? bias[r0] : 0.f;
        float bv1 = bias ? bias[r0 + 8] : 0.f;
        #pragma unroll
        for (int j = 0; j < 8; j++) {
            int cc = ncol + j * 8;
            if constexpr (sizeof(OutT) == 4) {
                *(float2*)(Cz + (long)r0 * N + cc) =
                    make_float2(acc[mi][j][0] + bv0, acc[mi][j][1] + bv0);
                *(float2*)(Cz + (long)(r0 + 8) * N + cc) =
                    make_float2(acc[mi][j][2] + bv1, acc[mi][j][3] + bv1);
            } else {
                *(__half2*)(Cz + (long)r0 * N + cc) =
                    __floats2half2_rn(acc[mi][j][0] + bv0, acc[mi][j][1] + bv0);
                *(__half2*)(Cz + (long)(r0 + 8) * N + cc) =
                    __floats2half2_rn(acc[mi][j][2] + bv1, acc[mi][j][3] + bv1);
            }
        }
    }
}

// ========== merged conversion kernel (x16 | wq16 | wkv) ==========
#define XBLK 16384
#define WQBLK 128
#define WKVBLK 512
__global__ __launch_bounds__(256) void conv_all_kernel(
    const float* __restrict__ x, const float* __restrict__ w_qkv,
    __half* __restrict__ x16, __half* __restrict__ wq16,
    __half* __restrict__ wkv)
{
    int bid = blockIdx.x;
    if (bid < XBLK) {
        long i = ((long)bid * 256 + threadIdx.x) * 8;
        float4 a = *(const float4*)(x + i);
        float4 b = *(const float4*)(x + i + 4);
        __half2 h0 = __floats2half2_rn(a.x, a.y), h1 = __floats2half2_rn(a.z, a.w);
        __half2 h2 = __floats2half2_rn(b.x, b.y), h3 = __floats2half2_rn(b.z, b.w);
        uint4 o;
        o.x = *(uint32_t*)&h0; o.y = *(uint32_t*)&h1;
        o.z = *(uint32_t*)&h2; o.w = *(uint32_t*)&h3;
        *(uint4*)(x16 + i) = o;
    } else if (bid < XBLK + WQBLK) {
        long i = ((long)(bid - XBLK) * 256 + threadIdx.x) * 8;
        float4 a = *(const float4*)(w_qkv + i);
        float4 b = *(const float4*)(w_qkv + i + 4);
        __half2 h0 = __floats2half2_rn(a.x, a.y), h1 = __floats2half2_rn(a.z, a.w);
        __half2 h2 = __floats2half2_rn(b.x, b.y), h3 = __floats2half2_rn(b.z, b.w);
        uint4 o;
        o.x = *(uint32_t*)&h0; o.y = *(uint32_t*)&h1;
        o.z = *(uint32_t*)&h2; o.w = *(uint32_t*)&h3;
        *(uint4*)(wq16 + i) = o;
    } else {
        int i = (bid - XBLK - WQBLK) * 256 + threadIdx.x;  // float4 groups
        int r_new = i >> 7;
        int colg = i & 127;
        int h = r_new >> 7, wr = r_new & 127;
        int src_row = (wr < 64) ? (HIDDEN + h * 64 + wr)
                                : (2 * HIDDEN + h * 64 + (wr - 64));
        float4 a = *(const float4*)(w_qkv + (long)src_row * CDIM + colg * 4);
        __half2 h0 = __floats2half2_rn(a.x, a.y), h1 = __floats2half2_rn(a.z, a.w);
        *(__half2*)(wkv + (long)r_new * CDIM + colg * 4)     = h0;
        *(__half2*)(wkv + (long)r_new * CDIM + colg * 4 + 2) = h1;
    }
}

// == Mcat[b][o][h*64+c] = sum_d w_out[o][h*64+d] * ctx_norm[b][h][c][d] ==
__global__ __launch_bounds__(256) void mcat_kernel(const float* __restrict__ wo,
                                                   const __half* __restrict__ part,
                                                   const float* __restrict__ sums,
                                                   __half* __restrict__ mcat)
{
    __shared__ float ctxs[64][66];
    __shared__ float wos[64][66];
    __shared__ float invs[64];
    int bh = blockIdx.x;
    int b = bh >> 3, h = bh & 7;
    int t = threadIdx.x;
    int og = (t >> 4) * 4, cg = (t & 15) * 4;

    if (t < 64) {
        float s = 0.f;
        #pragma unroll 8
        for (int sp = 0; sp < NSPLIT; sp++)
            s += sums[((long)sp * BH_TOT + bh) * 64 + t];
        invs[t] = 1.0f / s;
    }
    __syncthreads();
    for (int i0 = t * 2; i0 < 4096; i0 += 512) {
        float sx = 0.f, sy = 0.f;
        #pragma unroll 8
        for (int sp = 0; sp < NSPLIT; sp++) {
            __half2 hp = *(const __half2*)&part[((long)sp * BH_TOT + bh) * 4096 + i0];
            float2 f = __half22float2(hp);
            sx += f.x; sy += f.y;
        }
        int c = i0 >> 6, d = i0 & 63;
        ctxs[c][d]     = sx * invs[c];
        ctxs[c][d + 1] = sy * invs[c];
    }

    for (int o0 = 0; o0 < HIDDEN; o0 += 64) {
        __syncthreads();
        for (int i = t; i < 4096; i += 256)
            wos[i >> 6][i & 63] = wo[(long)(o0 + (i >> 6)) * HIDDEN + h * 64 + (i & 63)];
        __syncthreads();

        unsigned long long acc2[4][4];
        #pragma unroll
        for (int i = 0; i < 4; i++)
            #pragma unroll
            for (int j = 0; j < 4; j++) acc2[i][j] = 0ull;

        #pragma unroll 8
        for (int d2 = 0; d2 < 64; d2 += 2) {
            unsigned long long av[4], bv[4];
            #pragma unroll
            for (int i = 0; i < 4; i++)
                av[i] = *(const unsigned long long*)&wos[og + i][d2];
            #pragma unroll
            for (int j = 0; j < 4; j++)
                bv[j] = *(const unsigned long long*)&ctxs[cg + j][d2];
            #pragma unroll
            for (int i = 0; i < 4; i++)
                #pragma unroll
                for (int j = 0; j < 4; j++)
                    acc2[i][j] = f32x2_fma(av[i], bv[j], acc2[i][j]);
        }
        #pragma unroll
        for (int i = 0; i < 4; i++) {
            float r[4];
            #pragma unroll
            for (int j = 0; j < 4; j++) {
                float2 p = f32x2_unpack(acc2[i][j]);
                r[j] = p.x + p.y;
            }
            __half* dp = mcat + ((long)b * HIDDEN + o0 + og + i) * HIDDEN + h * 64 + cg;
            *(__half2*)(dp)     = __floats2half2_rn(r[0], r[1]);
            *(__half2*)(dp + 2) = __floats2half2_rn(r[2], r[3]);
        }
    }
}

// ================= launch =================
extern "C" void kernel_launch(void* const* d_in, const int* in_sizes, int n_in,
                              void* d_out, int out_size)
{
    const float* x     = (const float*)d_in[0];   // (16,512,64,64)
    const float* w_qkv = (const float*)d_in[1];   // (1536,512): [q;k;v]
    const float* w_out = (const float*)d_in[2];   // (512,512)
    const float* b_out = (const float*)d_in[3];   // (512,)
    float* y = (float*)d_out;

    float* sums;
    __half *x16, *part, *mcat, *mcomb, *wkv, *wq16;
    cudaGetSymbolAddress((void**)&x16,   g_x16);
    cudaGetSymbolAddress((void**)&part,  g_part);
    cudaGetSymbolAddress((void**)&sums,  g_sums);
    cudaGetSymbolAddress((void**)&mcat,  g_mcat);
    cudaGetSymbolAddress((void**)&mcomb, g_mcomb);
    cudaGetSymbolAddress((void**)&wkv,   g_wkv);
    cudaGetSymbolAddress((void**)&wq16,  g_wq16);

    cudaFuncSetAttribute(gemm1ctx_kernel,
                         cudaFuncAttributeMaxDynamicSharedMemorySize, GEMM_SMEM);
    cudaFuncSetAttribute(gemm_g_kernel<__half>,
                         cudaFuncAttributeMaxDynamicSharedMemorySize, GEMM_SMEM);
    cudaFuncSetAttribute(gemm_g_kernel<float>,
                         cudaFuncAttributeMaxDynamicSharedMemorySize, GEMM_SMEM);

    // 0. all conversions in one launch
    conv_all_kernel<<<XBLK + WQBLK + WKVBLK, 256>>>(x, w_qkv, x16, wq16, wkv);

    // 1. fused [k;v] GEMM + exp + ctx partials (HMMA) + row sums
    gemm1ctx_kernel<<<dim3(NSPLIT, HEADS, BATCH), 128, GEMM_SMEM>>>(
        wkv, x16, part, sums);

    // 2. Mcat = (W_out per-head) @ normalize(ctx)^T  (split-reduce fused)
    mcat_kernel<<<BH_TOT, 256>>>(w_out, part, sums, mcat);

    // 3. Mcomb[b] = Mcat[b] @ Wq   (B = Wq natural [k][n])
    gemm_g_kernel<__half><<<dim3(CDIM / 128, HIDDEN / 128, BATCH), 128, GEMM_SMEM>>>(
        mcat, wq16, mcomb, nullptr,
        HIDDEN, CDIM, HIDDEN,
        (long)HIDDEN * HIDDEN, 0L, (long)HIDDEN * CDIM);

    // 4. y = Mcomb @ x + b_out   (B = x16 natural [c][n])
    gemm_g_kernel<float><<<dim3(HW / 128, HIDDEN / 128, BATCH), 128, GEMM_SMEM>>>(
        mcomb, x16, y, b_out,
        HIDDEN, HW, CDIM,
        (long)HIDDEN * CDIM, (long)CDIM * HW, (long)HIDDEN * HW);
}